// round 17
// baseline (speedup 1.0000x reference)
#include <cuda_runtime.h>
#include <cstdint>

#define BATCH 64
#define FEAT  784
#define DIM   1001
#define DIMSQ (DIM * DIM)        // 1002001; DIM % 8 == 1, DIMSQ % 8 == 1
#define ROWS_PER_CTA 7
#define CTAS_X 143               // 143*7 = 1001 exactly

// 256-bit store (sm_100+): 8 x b32, requires 32B-aligned address.
#define STG256(p, a0,a1,a2,a3,a4,a5,a6,a7)                                     \
    asm volatile("st.global.v8.b32 [%0], {%1,%2,%3,%4,%5,%6,%7,%8};"           \
                 :: "l"(p),                                                    \
                    "r"(__float_as_uint(a0)), "r"(__float_as_uint(a1)),        \
                    "r"(__float_as_uint(a2)), "r"(__float_as_uint(a3)),        \
                    "r"(__float_as_uint(a4)), "r"(__float_as_uint(a5)),        \
                    "r"(__float_as_uint(a6)), "r"(__float_as_uint(a7))         \
                 : "memory")

// 64-thread CTAs; grid (143, 64, 2). CTA = (7 rows, batch b, row-half h).
// Row octets j = A8 + 8t, A8 = (-(b+i)) & 7, NQ = (A8<=1) ? 125 : 124.
//   half 0: t = tid in [0,64)        (always < NQ)  + head scalars [0,A8)
//   half 1: t = 64+tid, t < NQ       + tail zeros [A8+8*NQ, 1001)
// Thread window: w[0..15] = s[512*h + 8*tid .. +16).
__global__ void __launch_bounds__(64) amp_kernel(const float* __restrict__ x,
                                                 float* __restrict__ out) {
    __shared__ float s_sm[1032];           // scaled state, zero-padded past FEAT
    __shared__ float red[2];
    __shared__ float s_inv;

    const int tid = threadIdx.x;           // 0..63
    const int b   = blockIdx.y;
    const int h   = blockIdx.z;            // row half
    const float* xb = x + b * FEAT;                            // 16B-aligned
    const float4* xb4 = reinterpret_cast<const float4*>(xb);   // 196 float4s
    float4* s_sm4 = reinterpret_cast<float4*>(s_sm);           // 258 float4s

    // ---- vectorized norm: 196 = 64*3 + 4 float4 loads ----
    float4 q0 = xb4[tid];
    float4 q1 = xb4[tid + 64];
    float4 q2 = xb4[tid + 128];
    float4 q3 = make_float4(0.f, 0.f, 0.f, 0.f);
    if (tid < 4) q3 = xb4[tid + 192];
    float p = q0.x*q0.x + q0.y*q0.y + q0.z*q0.z + q0.w*q0.w
            + q1.x*q1.x + q1.y*q1.y + q1.z*q1.z + q1.w*q1.w
            + q2.x*q2.x + q2.y*q2.y + q2.z*q2.z + q2.w*q2.w
            + q3.x*q3.x + q3.y*q3.y + q3.z*q3.z + q3.w*q3.w;
    #pragma unroll
    for (int o = 16; o > 0; o >>= 1) p += __shfl_xor_sync(0xFFFFFFFFu, p, o);
    if ((tid & 31) == 0) red[tid >> 5] = p;
    __syncthreads();
    if (tid == 0) s_inv = rsqrtf(red[0] + red[1]);
    __syncthreads();
    const float inv = s_inv;

    {
        s_sm4[tid]       = make_float4(q0.x*inv, q0.y*inv, q0.z*inv, q0.w*inv);
        s_sm4[tid + 64]  = make_float4(q1.x*inv, q1.y*inv, q1.z*inv, q1.w*inv);
        s_sm4[tid + 128] = make_float4(q2.x*inv, q2.y*inv, q2.z*inv, q2.w*inv);
        const float4 z = make_float4(0.f, 0.f, 0.f, 0.f);
        s_sm4[tid + 192] = (tid < 4)
            ? make_float4(q3.x*inv, q3.y*inv, q3.z*inv, q3.w*inv) : z;
        if (tid < 2) s_sm4[tid + 256] = z;                     // idx 256,257
    }
    __syncthreads();

    // ---- register window: w[0..15] = s[512*h + 8*tid .. +16) ----
    float w[16];
    const int wbase = 512 * h + 8 * tid;
    #pragma unroll
    for (int q = 0; q < 4; q++) {
        const float4 a = *reinterpret_cast<const float4*>(&s_sm[wbase + 4 * q]);
        w[4*q+0] = a.x; w[4*q+1] = a.y; w[4*q+2] = a.z; w[4*q+3] = a.w;
    }

    const int i0   = blockIdx.x * ROWS_PER_CTA;
    const int iend = i0 + ROWS_PER_CTA;                        // exact: no clamp

    for (int i = i0; i < iend; ++i) {
        const float si = s_sm[i];                              // broadcast LDS
        float* rowp    = out + (size_t)b * DIMSQ + (size_t)i * DIM;
        const int A8   = (-(b + i)) & 7;

        if (h == 0) {
            // head scalars j in [0, A8)
            if (tid < A8) rowp[tid] = si * s_sm[tid];
            // octets t = tid in [0,64): always < NQ (>= 124)
            float* dst = rowp + A8 + 8 * tid;                  // 32B-aligned
            switch (A8) {
                #define C0(K) STG256(dst, si*w[(K)+0], si*w[(K)+1], si*w[(K)+2],  \
                                          si*w[(K)+3], si*w[(K)+4], si*w[(K)+5],  \
                                          si*w[(K)+6], si*w[(K)+7])
                case 0: C0(0); break;
                case 1: C0(1); break;
                case 2: C0(2); break;
                case 3: C0(3); break;
                case 4: C0(4); break;
                case 5: C0(5); break;
                case 6: C0(6); break;
                default: C0(7); break;
                #undef C0
            }
        } else {
            // octets t = 64 + tid, valid while t < NQ; plus tail zeros
            #define C1(K)                                                          \
                {                                                                  \
                    constexpr int NQ = ((K) <= 1) ? 125 : 124;                     \
                    constexpr int TS = (K) + 8 * NQ;      /* tail start */         \
                    if (tid < NQ - 64) {                                           \
                        float* dst = rowp + (K) + 8 * (64 + tid);                  \
                        STG256(dst, si*w[(K)+0], si*w[(K)+1], si*w[(K)+2],         \
                                    si*w[(K)+3], si*w[(K)+4], si*w[(K)+5],         \
                                    si*w[(K)+6], si*w[(K)+7]);                     \
                    }                                                              \
                    if (TS < DIM && tid >= 56 && tid < 56 + (DIM - TS))            \
                        rowp[TS + (tid - 56)] = 0.0f;                              \
                }
            switch (A8) {
                case 0: C1(0); break;
                case 1: C1(1); break;
                case 2: C1(2); break;
                case 3: C1(3); break;
                case 4: C1(4); break;
                case 5: C1(5); break;
                case 6: C1(6); break;
                default: C1(7); break;
            }
            #undef C1
        }
    }
}

extern "C" void kernel_launch(void* const* d_in, const int* in_sizes, int n_in,
                              void* d_out, int out_size) {
    const float* x   = (const float*)d_in[0];
    float*       out = (float*)d_out;
    amp_kernel<<<dim3(CTAS_X, BATCH, 2), 64>>>(x, out);
}